// round 4
// baseline (speedup 1.0000x reference)
#include <cuda_runtime.h>
#include <math.h>

#define B 16
#define LQ 2048
#define EMB1 1024
#define EMB2 768
#define HDIM 1024
#define NHEAD 16
#define DH 64
#define GRIDX 27   // 27*16 = 432 blocks <= 444 slots (148 SMs x 3 blocks)

// Scratch (static device globals; no allocation in kernel_launch).
__device__ float g_K[B * HDIM];
__device__ float g_V[B * HDIM];
__device__ float g_Weff[B * NHEAD * EMB1];
__device__ float g_c[B * NHEAD];

// Packed f32x2 FMA: acc = a*b + acc elementwise on (lo,hi) float pairs.
__device__ __forceinline__ void fma2(unsigned long long& acc,
                                     unsigned long long a, unsigned long long b) {
    asm("fma.rn.f32x2 %0, %1, %2, %0;" : "+l"(acc) : "l"(a), "l"(b));
}
__device__ __forceinline__ float unpack_sum(unsigned long long a) {
    float lo, hi;
    asm("mov.b64 {%0, %1}, %2;" : "=f"(lo), "=f"(hi) : "l"(a));
    return lo + hi;
}

// ---------------------------------------------------------------------------
// Kernel 1: block per output column j (1024 blocks, 512 thr = 16 warps).
// Wk/Wv row j staged in smem once; warp b computes K[b,j], V[b,j].
// ---------------------------------------------------------------------------
__global__ __launch_bounds__(512) void kv_kernel(const float* __restrict__ emb2,
                          const float* __restrict__ Wk, const float* __restrict__ bk,
                          const float* __restrict__ Wv, const float* __restrict__ bv) {
    __shared__ float4 wk_s[EMB2 / 4], wv_s[EMB2 / 4];
    int j = blockIdx.x;
    int tid = threadIdx.x;

    if (tid < EMB2 / 4)
        wk_s[tid] = ((const float4*)(Wk + j * EMB2))[tid];
    else if (tid < EMB2 / 2)
        wv_s[tid - EMB2 / 4] = ((const float4*)(Wv + j * EMB2))[tid - EMB2 / 4];
    __syncthreads();

    int b = tid >> 5, lane = tid & 31;
    const float4* e4 = (const float4*)(emb2 + b * EMB2);

    float ak = 0.f, av = 0.f;
#pragma unroll
    for (int i = 0; i < 6; i++) {
        float4 e = __ldg(&e4[i * 32 + lane]);
        float4 k = wk_s[i * 32 + lane];
        float4 v = wv_s[i * 32 + lane];
        ak = fmaf(e.x, k.x, ak); ak = fmaf(e.y, k.y, ak);
        ak = fmaf(e.z, k.z, ak); ak = fmaf(e.w, k.w, ak);
        av = fmaf(e.x, v.x, av); av = fmaf(e.y, v.y, av);
        av = fmaf(e.z, v.z, av); av = fmaf(e.w, v.w, av);
    }
#pragma unroll
    for (int off = 16; off; off >>= 1) {
        ak += __shfl_xor_sync(0xffffffffu, ak, off);
        av += __shfl_xor_sync(0xffffffffu, av, off);
    }
    if (lane == 0) {
        g_K[b * HDIM + j] = ak + bk[j];
        g_V[b * HDIM + j] = av + bv[j];
    }
}

// ---------------------------------------------------------------------------
// Kernel 2: Weff[b,h,e] = sum_d Wq[h*64+d, e] * K[b, h*64+d].
// Grid (8 e-chunks, 16 heads, 4 b-groups); folds c[b,h] on (0,h,0) blocks.
// ---------------------------------------------------------------------------
__global__ void weff_kernel(const float* __restrict__ Wq, const float* __restrict__ bq) {
    __shared__ float Wq_s[DH * 128];
    __shared__ float Ks[DH];
    int h = blockIdx.y;
    int e0 = blockIdx.x * 128;
    int bg = blockIdx.z;
    int tid = threadIdx.x;

    if (blockIdx.x == 0 && bg == 0 && tid < B) {
        float a = 0.f;
#pragma unroll 16
        for (int d = 0; d < DH; d++)
            a = fmaf(bq[h * DH + d], g_K[tid * HDIM + h * DH + d], a);
        g_c[tid * NHEAD + h] = a;
    }

#pragma unroll 8
    for (int d = 0; d < DH; d++)
        Wq_s[d * 128 + tid] = Wq[(h * DH + d) * EMB1 + e0 + tid];

    for (int bb = 0; bb < 4; bb++) {
        int b = bg * 4 + bb;
        __syncthreads();
        if (tid < DH) Ks[tid] = g_K[b * HDIM + h * DH + tid];
        __syncthreads();
        float a = 0.f;
#pragma unroll 16
        for (int d = 0; d < DH; d++)
            a = fmaf(Wq_s[d * 128 + tid], Ks[d], a);
        g_Weff[(b * NHEAD + h) * EMB1 + e0 + tid] = a;
    }
}

// ---------------------------------------------------------------------------
// Kernel 3 (main): warp processes 4-row quads, 2 passes of 8 heads each.
// Each w fetched from smem feeds 4 rows (smem traffic halved vs pairs);
// FFMA2 (fma.rn.f32x2) halves FP issue with zero pack cost because both
// emb1 and Weff are loaded as ulonglong2 (natural f32-pair registers).
// ---------------------------------------------------------------------------
__global__ __launch_bounds__(192, 3) void main_kernel(const float* __restrict__ emb1,
                                                      float* __restrict__ out) {
    extern __shared__ float sm[];
    float* Weff_s = sm;                    // 16384 floats
    float* V_s = sm + NHEAD * EMB1;        // 1024 floats
    float* c_s = V_s + HDIM;               // 16 floats

    int b = blockIdx.y;
    int tid = threadIdx.x;

    // Cooperative staging of Weff[b], V[b], c[b]
    {
        const float4* Wg = (const float4*)(g_Weff + (size_t)b * NHEAD * EMB1);
        float4* Ws4 = (float4*)Weff_s;
        for (int i = tid; i < NHEAD * EMB1 / 4; i += 192)
            Ws4[i] = Wg[i];
        const float4* Vg = (const float4*)(g_V + (size_t)b * HDIM);
        for (int i = tid; i < HDIM / 4; i += 192)
            ((float4*)V_s)[i] = Vg[i];
        if (tid < NHEAD) c_s[tid] = g_c[b * NHEAD + tid];
    }
    __syncthreads();

    int warp = tid >> 5, lane = tid & 31;
    const ulonglong2* Wsd = (const ulonglong2*)Weff_s;
    const float4* Vs4 = (const float4*)V_s;
    int hi = lane >> 4;

    // Row quads: 512 per batch over 27 blocks x 6 warps = 162 warps.
    for (int qd = blockIdx.x * 6 + warp; qd < LQ / 4; qd += GRIDX * 6) {
        const ulonglong2* xb = (const ulonglong2*)(emb1 + ((size_t)b * LQ + qd * 4) * EMB1);
        float4* ob = (float4*)(out + ((size_t)b * LQ + qd * 4) * EMB1);

#pragma unroll
        for (int pass = 0; pass < 2; pass++) {
            unsigned long long acc[4][8];
#pragma unroll
            for (int r = 0; r < 4; r++)
#pragma unroll
                for (int h = 0; h < 8; h++) acc[r][h] = 0ull;

#pragma unroll
            for (int i = 0; i < 8; i++) {
                ulonglong2 x[4];
#pragma unroll
                for (int r = 0; r < 4; r++)
                    x[r] = __ldg(xb + r * (EMB1 / 4) + i * 32 + lane);
#pragma unroll
                for (int h = 0; h < 8; h++) {
                    ulonglong2 w = Wsd[(pass * 8 + h) * 256 + i * 32 + lane];
#pragma unroll
                    for (int r = 0; r < 4; r++) {
                        fma2(acc[r][h], x[r].x, w.x);
                        fma2(acc[r][h], x[r].y, w.y);
                    }
                }
            }

            // Reduce 8 head-partials x 32 lanes -> lane l holds head (l&7).
            float sig[4];
#pragma unroll
            for (int r = 0; r < 4; r++) {
                float v[8];
#pragma unroll
                for (int h = 0; h < 8; h++) v[h] = unpack_sum(acc[r][h]);
#pragma unroll
                for (int s = 0; s < 3; s++) {
                    int o = 1 << s;
                    int bit = (lane >> s) & 1;
#pragma unroll
                    for (int j = 0; j < (4 >> s); j++) {
                        float keep = bit ? v[2 * j + 1] : v[2 * j];
                        float send = bit ? v[2 * j] : v[2 * j + 1];
                        v[j] = keep + __shfl_xor_sync(0xffffffffu, send, o);
                    }
                }
                v[0] += __shfl_xor_sync(0xffffffffu, v[0], 8);
                v[0] += __shfl_xor_sync(0xffffffffu, v[0], 16);
                float a = v[0] + c_s[(lane & 7) + pass * 8];
                sig[r] = __fdividef(1.f, 1.f + __expf(-a));
            }

            // Store the half of the row this pass covers (heads 8p..8p+7).
#pragma unroll
            for (int i2 = 0; i2 < 4; i2++) {
                int i = pass * 4 + i2;          // float4 chunk; head = 2i + hi
                int src = 2 * i2 + hi;           // lane holding that head
                float4 vv = Vs4[i * 32 + lane];
#pragma unroll
                for (int r = 0; r < 4; r++) {
                    float s = __shfl_sync(0xffffffffu, sig[r], src);
                    float4 o;
                    o.x = s * vv.x; o.y = s * vv.y; o.z = s * vv.z; o.w = s * vv.w;
                    ob[r * (EMB1 / 4) + i * 32 + lane] = o;
                }
            }
        }
    }
}

// ---------------------------------------------------------------------------
extern "C" void kernel_launch(void* const* d_in, const int* in_sizes, int n_in,
                              void* d_out, int out_size) {
    const float* emb1 = (const float*)d_in[0];
    const float* emb2 = (const float*)d_in[1];
    const float* Wq   = (const float*)d_in[2];
    const float* bq   = (const float*)d_in[3];
    const float* Wk   = (const float*)d_in[4];
    const float* bk   = (const float*)d_in[5];
    const float* Wv   = (const float*)d_in[6];
    const float* bv   = (const float*)d_in[7];
    float* out = (float*)d_out;

    kv_kernel<<<HDIM, 512>>>(emb2, Wk, bk, Wv, bv);
    weff_kernel<<<dim3(EMB1 / 128, NHEAD, 4), 128>>>(Wq, bq);

    int smem = (NHEAD * EMB1 + HDIM + NHEAD) * (int)sizeof(float);
    static bool attr_set = false;
    if (!attr_set) {
        cudaFuncSetAttribute(main_kernel, cudaFuncAttributeMaxDynamicSharedMemorySize, smem);
        attr_set = true;
    }
    main_kernel<<<dim3(GRIDX, B), 192, smem>>>(emb1, out);
}

// round 5
// speedup vs baseline: 2.6647x; 2.6647x over previous
#include <cuda_runtime.h>
#include <math.h>

#define B 16
#define LQ 2048
#define EMB1 1024
#define EMB2 768
#define HDIM 1024
#define NHEAD 16
#define DH 64
#define GRIDX 18   // 18*16 = 288 blocks <= 296 slots (148 SMs x 2 blocks)

// Scratch (static device globals; no allocation in kernel_launch).
__device__ float g_K[B * HDIM];
__device__ float g_V[B * HDIM];
__device__ float g_Weff[B * NHEAD * EMB1];
__device__ float g_c[B * NHEAD];

// Packed f32x2 FMA: acc = a*b + acc elementwise on (lo,hi) float pairs.
__device__ __forceinline__ void fma2(unsigned long long& acc,
                                     unsigned long long a, unsigned long long b) {
    asm("fma.rn.f32x2 %0, %1, %2, %0;" : "+l"(acc) : "l"(a), "l"(b));
}
__device__ __forceinline__ float unpack_sum(unsigned long long a) {
    float lo, hi;
    asm("mov.b64 {%0, %1}, %2;" : "=f"(lo), "=f"(hi) : "l"(a));
    return lo + hi;
}

// ---------------------------------------------------------------------------
// Kernel 1: block per output column j (1024 blocks, 512 thr = 16 warps).
// Wk/Wv row j staged in smem once; warp b computes K[b,j], V[b,j].
// ---------------------------------------------------------------------------
__global__ __launch_bounds__(512) void kv_kernel(const float* __restrict__ emb2,
                          const float* __restrict__ Wk, const float* __restrict__ bk,
                          const float* __restrict__ Wv, const float* __restrict__ bv) {
    __shared__ float4 wk_s[EMB2 / 4], wv_s[EMB2 / 4];
    int j = blockIdx.x;
    int tid = threadIdx.x;

    if (tid < EMB2 / 4)
        wk_s[tid] = ((const float4*)(Wk + j * EMB2))[tid];
    else if (tid < EMB2 / 2)
        wv_s[tid - EMB2 / 4] = ((const float4*)(Wv + j * EMB2))[tid - EMB2 / 4];
    __syncthreads();

    int b = tid >> 5, lane = tid & 31;
    const float4* e4 = (const float4*)(emb2 + b * EMB2);

    float ak = 0.f, av = 0.f;
#pragma unroll
    for (int i = 0; i < 6; i++) {
        float4 e = __ldg(&e4[i * 32 + lane]);
        float4 k = wk_s[i * 32 + lane];
        float4 v = wv_s[i * 32 + lane];
        ak = fmaf(e.x, k.x, ak); ak = fmaf(e.y, k.y, ak);
        ak = fmaf(e.z, k.z, ak); ak = fmaf(e.w, k.w, ak);
        av = fmaf(e.x, v.x, av); av = fmaf(e.y, v.y, av);
        av = fmaf(e.z, v.z, av); av = fmaf(e.w, v.w, av);
    }
#pragma unroll
    for (int off = 16; off; off >>= 1) {
        ak += __shfl_xor_sync(0xffffffffu, ak, off);
        av += __shfl_xor_sync(0xffffffffu, av, off);
    }
    if (lane == 0) {
        g_K[b * HDIM + j] = ak + bk[j];
        g_V[b * HDIM + j] = av + bv[j];
    }
}

// ---------------------------------------------------------------------------
// Kernel 2: Weff[b,h,e] = sum_d Wq[h*64+d, e] * K[b, h*64+d].
// Grid (8 e-chunks, 16 heads, 4 b-groups); folds c[b,h] on (0,h,0) blocks.
// ---------------------------------------------------------------------------
__global__ void weff_kernel(const float* __restrict__ Wq, const float* __restrict__ bq) {
    __shared__ float Wq_s[DH * 128];
    __shared__ float Ks[DH];
    int h = blockIdx.y;
    int e0 = blockIdx.x * 128;
    int bg = blockIdx.z;
    int tid = threadIdx.x;

    if (blockIdx.x == 0 && bg == 0 && tid < B) {
        float a = 0.f;
#pragma unroll 16
        for (int d = 0; d < DH; d++)
            a = fmaf(bq[h * DH + d], g_K[tid * HDIM + h * DH + d], a);
        g_c[tid * NHEAD + h] = a;
    }

#pragma unroll 8
    for (int d = 0; d < DH; d++)
        Wq_s[d * 128 + tid] = Wq[(h * DH + d) * EMB1 + e0 + tid];

    for (int bb = 0; bb < 4; bb++) {
        int b = bg * 4 + bb;
        __syncthreads();
        if (tid < DH) Ks[tid] = g_K[b * HDIM + h * DH + tid];
        __syncthreads();
        float a = 0.f;
#pragma unroll 16
        for (int d = 0; d < DH; d++)
            a = fmaf(Wq_s[d * 128 + tid], Ks[d], a);
        g_Weff[(b * NHEAD + h) * EMB1 + e0 + tid] = a;
    }
}

// ---------------------------------------------------------------------------
// Kernel 3 (main): R3 structure (row pairs, prefetched x, single 16-head
// pass, folded reduction) + FFMA2 arithmetic. (256,2) launch bounds give
// 128 regs -> the 64-reg u64 accumulator file + 16 prefetch regs fit with
// zero spills; smem 68KB also caps at 2 blocks/SM -> occupancy limiter
// consistent. Grid 288 = exactly one wave at 2 blocks/SM.
// ---------------------------------------------------------------------------
__global__ __launch_bounds__(256, 2) void main_kernel(const float* __restrict__ emb1,
                                                      float* __restrict__ out) {
    extern __shared__ float sm[];
    float* Weff_s = sm;                    // 16384 floats
    float* V_s = sm + NHEAD * EMB1;        // 1024 floats
    float* c_s = V_s + HDIM;               // 16 floats

    int b = blockIdx.y;
    int tid = threadIdx.x;

    // Cooperative staging of Weff[b], V[b], c[b]
    {
        const float4* Wg = (const float4*)(g_Weff + (size_t)b * NHEAD * EMB1);
        float4* Ws4 = (float4*)Weff_s;
#pragma unroll
        for (int i = 0; i < NHEAD * EMB1 / 4 / 256; i++)
            Ws4[i * 256 + tid] = Wg[i * 256 + tid];
        const float4* Vg = (const float4*)(g_V + (size_t)b * HDIM);
        if (tid < HDIM / 4) ((float4*)V_s)[tid] = Vg[tid];
        if (tid < NHEAD) c_s[tid] = g_c[b * NHEAD + tid];
    }
    __syncthreads();

    int warp = tid >> 5, lane = tid & 31;
    const ulonglong2* Wsd = (const ulonglong2*)Weff_s;
    const float4* Vs4 = (const float4*)V_s;
    int hi = lane >> 4;
    float c_l = c_s[lane & 15];

    // Row pairs: 1024 per batch over 18 blocks x 8 warps = 144 warps.
    for (int p = blockIdx.x * 8 + warp; p < LQ / 2; p += GRIDX * 8) {
        const ulonglong2* x0p = (const ulonglong2*)(emb1 + ((size_t)b * LQ + 2 * p) * EMB1);
        const ulonglong2* x1p = x0p + EMB1 / 4;

        ulonglong2 x0 = __ldg(x0p + lane);
        ulonglong2 x1 = __ldg(x1p + lane);

        unsigned long long acc0[NHEAD], acc1[NHEAD];
#pragma unroll
        for (int h = 0; h < NHEAD; h++) { acc0[h] = 0ull; acc1[h] = 0ull; }

#pragma unroll
        for (int i = 0; i < 8; i++) {
            ulonglong2 x0n, x1n;
            if (i < 7) {                               // prefetch next chunk
                x0n = __ldg(x0p + (i + 1) * 32 + lane);
                x1n = __ldg(x1p + (i + 1) * 32 + lane);
            }
#pragma unroll
            for (int h = 0; h < NHEAD; h++) {
                ulonglong2 w = Wsd[h * 256 + i * 32 + lane];
                fma2(acc0[h], x0.x, w.x);
                fma2(acc0[h], x0.y, w.y);
                fma2(acc1[h], x1.x, w.x);
                fma2(acc1[h], x1.y, w.y);
            }
            if (i < 7) { x0 = x0n; x1 = x1n; }
        }

        // Unpack f32x2 partials, then folded reduction: lane l -> head (l&15).
        float v0[NHEAD], v1[NHEAD];
#pragma unroll
        for (int h = 0; h < NHEAD; h++) {
            v0[h] = unpack_sum(acc0[h]);
            v1[h] = unpack_sum(acc1[h]);
        }
#pragma unroll
        for (int s = 0; s < 4; s++) {
            int o = 1 << s;
            int bit = (lane >> s) & 1;
#pragma unroll
            for (int j = 0; j < (8 >> s); j++) {
                float k0 = bit ? v0[2 * j + 1] : v0[2 * j];
                float s0 = bit ? v0[2 * j] : v0[2 * j + 1];
                v0[j] = k0 + __shfl_xor_sync(0xffffffffu, s0, o);
                float k1 = bit ? v1[2 * j + 1] : v1[2 * j];
                float s1 = bit ? v1[2 * j] : v1[2 * j + 1];
                v1[j] = k1 + __shfl_xor_sync(0xffffffffu, s1, o);
            }
        }
        v0[0] += __shfl_xor_sync(0xffffffffu, v0[0], 16);
        v1[0] += __shfl_xor_sync(0xffffffffu, v1[0], 16);

        float sig0 = __fdividef(1.f, 1.f + __expf(-(v0[0] + c_l)));
        float sig1 = __fdividef(1.f, 1.f + __expf(-(v1[0] + c_l)));

        float4* o0 = (float4*)(out + ((size_t)b * LQ + 2 * p) * EMB1);
        float4* o1 = o0 + EMB1 / 4;
#pragma unroll
        for (int i = 0; i < 8; i++) {
            // float4 (i*32+lane) belongs to head 2i + hi; lane (2i+hi) holds it.
            float s0 = __shfl_sync(0xffffffffu, sig0, 2 * i + hi);
            float s1 = __shfl_sync(0xffffffffu, sig1, 2 * i + hi);
            float4 v = Vs4[i * 32 + lane];
            float4 r0, r1;
            r0.x = s0 * v.x; r0.y = s0 * v.y; r0.z = s0 * v.z; r0.w = s0 * v.w;
            r1.x = s1 * v.x; r1.y = s1 * v.y; r1.z = s1 * v.z; r1.w = s1 * v.w;
            o0[i * 32 + lane] = r0;
            o1[i * 32 + lane] = r1;
        }
    }
}

// ---------------------------------------------------------------------------
extern "C" void kernel_launch(void* const* d_in, const int* in_sizes, int n_in,
                              void* d_out, int out_size) {
    const float* emb1 = (const float*)d_in[0];
    const float* emb2 = (const float*)d_in[1];
    const float* Wq   = (const float*)d_in[2];
    const float* bq   = (const float*)d_in[3];
    const float* Wk   = (const float*)d_in[4];
    const float* bk   = (const float*)d_in[5];
    const float* Wv   = (const float*)d_in[6];
    const float* bv   = (const float*)d_in[7];
    float* out = (float*)d_out;

    kv_kernel<<<HDIM, 512>>>(emb2, Wk, bk, Wv, bv);
    weff_kernel<<<dim3(EMB1 / 128, NHEAD, 4), 128>>>(Wq, bq);

    int smem = (NHEAD * EMB1 + HDIM + NHEAD) * (int)sizeof(float);
    static bool attr_set = false;
    if (!attr_set) {
        cudaFuncSetAttribute(main_kernel, cudaFuncAttributeMaxDynamicSharedMemorySize, smem);
        attr_set = true;
    }
    main_kernel<<<dim3(GRIDX, B), 256, smem>>>(emb1, out);
}